// round 4
// baseline (speedup 1.0000x reference)
#include <cuda_runtime.h>
#include <cuda_fp16.h>
#include <cstdint>

// ---------------- problem constants ----------------
#define HID        256
#define OBS_STRIDE 54
#define SELF_OBS   18
#define NBR        6
#define BATCH_N    131072
#define TILE_B     16                    // batches per CTA iteration
#define NTILES     (BATCH_N / TILE_B)    // 8192
#define THREADS    256                   // 8 warps: warp h owns hidden cols [32h, 32h+32)
#define GRID_X     152

// ==================== helpers ====================
static __device__ __forceinline__ float tanha(float x) {
    float y;
    asm("tanh.approx.f32 %0, %1;" : "=f"(y) : "f"(x));
    return y;
}
static __device__ __forceinline__ uint32_t packh2(float a, float b) {
    __half2 h = __floats2half2_rn(a, b);
    return *reinterpret_cast<uint32_t*>(&h);
}
// D[16x8] += A[16x8] * B[8x8]   (f16 in, f32 accum)
static __device__ __forceinline__ void mma_k8(float& d0, float& d1, float& d2, float& d3,
                                              uint32_t a0, uint32_t a1, uint32_t b0) {
    asm volatile("mma.sync.aligned.m16n8k8.row.col.f32.f16.f16.f32 "
                 "{%0,%1,%2,%3}, {%4,%5}, {%6}, {%0,%1,%2,%3};"
                 : "+f"(d0), "+f"(d1), "+f"(d2), "+f"(d3)
                 : "r"(a0), "r"(a1), "r"(b0));
}
// D[16x8] += A[16x16] * B[16x8]
static __device__ __forceinline__ void mma_k16(float* d,
                                               uint32_t a0, uint32_t a1, uint32_t a2, uint32_t a3,
                                               uint32_t b0, uint32_t b1) {
    asm volatile("mma.sync.aligned.m16n8k16.row.col.f32.f16.f16.f32 "
                 "{%0,%1,%2,%3}, {%4,%5,%6,%7}, {%8,%9}, {%0,%1,%2,%3};"
                 : "+f"(d[0]), "+f"(d[1]), "+f"(d[2]), "+f"(d[3])
                 : "r"(a0), "r"(a1), "r"(a2), "r"(a3), "r"(b0), "r"(b1));
}

// ==================== kernel ====================
__global__ void __launch_bounds__(THREADS, 1)
deepsets_kernel(const float* __restrict__ obs,
                const float* __restrict__ W1,
                const float* __restrict__ b1,
                const float* __restrict__ W2,
                const float* __restrict__ b2,
                float* __restrict__ out)
{
    // x staging: [neighbor][row(batch)][k] fp16, k padded 6->8
    __shared__ __half xs[NBR][TILE_B][8];
    // W1 transposed: [n][k8] fp16
    __shared__ __half w1t[HID][8];
    // A-fragment exchange, double buffered: [buf][k-chunk][lane] 16B
    __shared__ uint4 exch[2][16][32];

    const int tid  = threadIdx.x;
    const int h    = tid >> 5;      // warp id = hidden n-slice
    const int lane = tid & 31;
    const int gid  = lane >> 2;     // fragment row group (0..7)
    const int tig  = lane & 3;      // thread-in-group
    const int n0   = h * 32;

    // ---- stage W1^T into smem (zero-pad k=6,7) ----
    for (int i = tid; i < HID * 8; i += THREADS) {
        int n = i >> 3, k = i & 7;
        w1t[n][k] = (k < 6) ? __float2half(W1[k * HID + n]) : __float2half(0.0f);
    }

    // ---- per-thread bias fragments ----
    float2 b1v[4], b2v[4];
    #pragma unroll
    for (int j = 0; j < 4; j++) {
        int c1 = (h * 4 + j) * 8 + 2 * tig;       // layer-1 tile cols (this warp's hidden range)
        b1v[j] = make_float2(b1[c1], b1[c1 + 1]);
        int c2 = n0 + j * 8 + 2 * tig;            // layer-2 output cols
        b2v[j] = make_float2(b2[c2], b2[c2 + 1]);
    }

    // ---- resident W2 B-fragments: warp h holds W2[:, n0..n0+31] ----
    // frag (c,t): b_lo = (k=16c+2tig, 16c+2tig+1; n = n0+8t+gid), b_hi = k+8
    uint32_t blo[16][4], bhi[16][4];
    #pragma unroll
    for (int c = 0; c < 16; c++) {
        #pragma unroll
        for (int t = 0; t < 4; t++) {
            int n = n0 + t * 8 + gid;
            int k = c * 16 + 2 * tig;
            blo[c][t] = packh2(W2[k * HID + n],       W2[(k + 1) * HID + n]);
            bhi[c][t] = packh2(W2[(k + 8) * HID + n], W2[(k + 9) * HID + n]);
        }
    }
    __syncthreads();   // w1t ready

    const float inv6 = 1.0f / 6.0f;

    for (int tile = blockIdx.x; tile < NTILES; tile += gridDim.x) {
        // ---- stage x (neighbor obs) for 16 batches ----
        for (int i = tid; i < NBR * TILE_B * 6; i += THREADS) {
            int k  = i % 6;
            int r  = (i / 6) % TILE_B;
            int nb = i / (6 * TILE_B);
            long b = (long)tile * TILE_B + r;
            xs[nb][r][k] = __float2half(obs[b * OBS_STRIDE + SELF_OBS + nb * 6 + k]);
        }
        if (tid < NBR * TILE_B) {   // zero pad k = 6,7
            *reinterpret_cast<uint32_t*>(&xs[tid / TILE_B][tid % TILE_B][6]) = 0u;
        }
        __syncthreads();

        float acc[4][4];
        #pragma unroll
        for (int t = 0; t < 4; t++)
            #pragma unroll
            for (int i = 0; i < 4; i++) acc[t][i] = 0.0f;

        #pragma unroll 1
        for (int nb = 0; nb < NBR; nb++) {
            const int buf = nb & 1;

            // ---- layer 1: h1[16 rows x 32 hidden] via mma.k8, pack to A-frags ----
            uint32_t xa0 = *reinterpret_cast<const uint32_t*>(&xs[nb][gid][2 * tig]);
            uint32_t xa1 = *reinterpret_cast<const uint32_t*>(&xs[nb][gid + 8][2 * tig]);
            uint4 pk0, pk1;
            {
                uint32_t* pk = reinterpret_cast<uint32_t*>(&pk0);
                #pragma unroll
                for (int j = 0; j < 4; j++) {
                    if (j == 2) pk = reinterpret_cast<uint32_t*>(&pk1);
                    int tt = h * 4 + j;            // global hidden n8-tile
                    uint32_t bb = *reinterpret_cast<const uint32_t*>(&w1t[tt * 8 + gid][2 * tig]);
                    float d0 = 0.f, d1 = 0.f, d2 = 0.f, d3 = 0.f;
                    mma_k8(d0, d1, d2, d3, xa0, xa1, bb);
                    d0 += b1v[j].x; d1 += b1v[j].y;
                    d2 += b1v[j].x; d3 += b1v[j].y;
                    // tile j even -> R0(row gid,klo),R1(row gid+8,klo); odd -> R2,R3 (khi)
                    pk[(j & 1) * 2 + 0] = packh2(tanha(d0), tanha(d1));
                    pk[(j & 1) * 2 + 1] = packh2(tanha(d2), tanha(d3));
                }
            }
            exch[buf][2 * h + 0][lane] = pk0;
            exch[buf][2 * h + 1][lane] = pk1;
            __syncthreads();   // all A-fragments of this neighbor visible

            // ---- layer 2: D[16 x 32] = h1[16 x 256] @ W2[:, n0..n0+31] ----
            float D[4][4];
            #pragma unroll
            for (int t = 0; t < 4; t++)
                #pragma unroll
                for (int i = 0; i < 4; i++) D[t][i] = 0.0f;

            #pragma unroll
            for (int c = 0; c < 16; c++) {
                uint4 a = exch[buf][c][lane];
                #pragma unroll
                for (int t = 0; t < 4; t++)
                    mma_k16(D[t], a.x, a.y, a.z, a.w, blo[c][t], bhi[c][t]);
            }

            // ---- epilogue: acc += tanh(D + b2) ----
            #pragma unroll
            for (int t = 0; t < 4; t++) {
                acc[t][0] += tanha(D[t][0] + b2v[t].x);
                acc[t][1] += tanha(D[t][1] + b2v[t].y);
                acc[t][2] += tanha(D[t][2] + b2v[t].x);
                acc[t][3] += tanha(D[t][3] + b2v[t].y);
            }
        }

        // ---- mean over neighbors, write out ----
        long b = (long)tile * TILE_B;
        #pragma unroll
        for (int t = 0; t < 4; t++) {
            int col = n0 + t * 8 + 2 * tig;
            float2 v0 = make_float2(acc[t][0] * inv6, acc[t][1] * inv6);
            float2 v1 = make_float2(acc[t][2] * inv6, acc[t][3] * inv6);
            *reinterpret_cast<float2*>(&out[(b + gid)     * HID + col]) = v0;
            *reinterpret_cast<float2*>(&out[(b + gid + 8) * HID + col]) = v1;
        }
        __syncthreads();   // protect xs/exch before next iteration's refill
    }
}

// ==================== launch ====================
extern "C" void kernel_launch(void* const* d_in, const int* in_sizes, int n_in,
                              void* d_out, int out_size) {
    // inputs: self_obs(131072*18), obs(131072*54), W1(6*256), b1(256), W2(256*256), b2(256)
    const float* obs = nullptr;
    const float* W1  = nullptr;
    const float* b1  = nullptr;
    const float* W2  = nullptr;
    const float* b2  = nullptr;
    for (int i = 0; i < n_in; i++) {
        int sz = in_sizes[i];
        if (sz == BATCH_N * OBS_STRIDE)  obs = (const float*)d_in[i];
        else if (sz == 6 * HID)          W1  = (const float*)d_in[i];
        else if (sz == HID * HID)        W2  = (const float*)d_in[i];
        else if (sz == HID) {
            if (!b1) b1 = (const float*)d_in[i];
            else if (!b2) b2 = (const float*)d_in[i];
        }
    }
    float* out = (float*)d_out;
    deepsets_kernel<<<GRID_X, THREADS>>>(obs, W1, b1, W2, b2, out);
}